// round 14
// baseline (speedup 1.0000x reference)
#include <cuda_runtime.h>
#include <cuda_fp16.h>
#include <cstdint>

#define NB   16
#define CIN  512
#define COUT 512
#define HID  512
#define HH   64
#define WW   64
#define NT   16384                 // 16 batches x 32x32 output tiles

// GEMM tiling (per Winograd coordinate): M=COUT, N=NT, K=CIN
#define KC     64
#define NCH    (CIN / KC)          // 8
#define TILEB  (128 * KC * 2)      // 16384 B
#define STAGEB (2 * TILEB)
#define NSTAGE 3
#define DYN_GEMM (NSTAGE * STAGEB) // 96 KB

// in_tf: 16 channels per CTA, paired-channel half2 stage writes
#define XS_STRIDE 72               // floats per row: [3 pad][w=-1..64][3 pad]
#define XS_BYTES  (16 * 4 * XS_STRIDE * 4)        // 18432
#define STG_PAD   24               // halfs per stage row (16 + 8 pad, 48B)
#define STG_BYTES (16 * 32 * STG_PAD * 2)         // 24576
#define DYN_INTF  (XS_BYTES + STG_BYTES)          // 43008

// ---------------- static device scratch -------------------------------------
__device__ float g_s[NB * CIN];
__device__ float g_d[NB * COUT];
__device__ float g_w2[CIN * COUT];
__device__ __half g_U[(size_t)16 * COUT * CIN];   // [coord][o][i]
__device__ __half g_V[(size_t)16 * 32 * NT * 16]; // [coord][ic16][tile][16ch]
__device__ __half g_M[(size_t)16 * COUT * NT];    // [coord][o][tile], fp16

// ---------------- helpers ----------------------------------------------------
__device__ __forceinline__ uint32_t s2u(const void* p) {
    uint32_t a;
    asm("{ .reg .u64 t; cvta.to.shared.u64 t, %1; cvt.u32.u64 %0, t; }" : "=r"(a) : "l"(p));
    return a;
}
__device__ __forceinline__ void cp_ca16(uint32_t dst, const void* src) {
    asm volatile("cp.async.ca.shared.global [%0], [%1], 16;"
                 :: "r"(dst), "l"(src) : "memory");
}
__device__ __forceinline__ void cp_cg16(uint32_t dst, const void* src) {
    asm volatile("cp.async.cg.shared.global [%0], [%1], 16;"
                 :: "r"(dst), "l"(src) : "memory");
}
__device__ __forceinline__ void cp_commit() {
    asm volatile("cp.async.commit_group;" ::: "memory");
}
__device__ __forceinline__ void cp_wait1() {
    asm volatile("cp.async.wait_group 1;" ::: "memory");
}
__device__ __forceinline__ void cp_wait0() {
    asm volatile("cp.async.wait_group 0;" ::: "memory");
}
__device__ __forceinline__ void ldsm4(uint32_t* r, uint32_t addr) {
    asm volatile("ldmatrix.sync.aligned.m8n8.x4.shared.b16 {%0,%1,%2,%3}, [%4];"
                 : "=r"(r[0]), "=r"(r[1]), "=r"(r[2]), "=r"(r[3]) : "r"(addr));
}
#define MMA(c, a, B0, B1) \
    asm volatile("mma.sync.aligned.m16n8k16.row.col.f32.f16.f16.f32 " \
                 "{%0,%1,%2,%3},{%4,%5,%6,%7},{%8,%9},{%0,%1,%2,%3};" \
                 : "+f"((c)[0]), "+f"((c)[1]), "+f"((c)[2]), "+f"((c)[3]) \
                 : "r"((a)[0]), "r"((a)[1]), "r"((a)[2]), "r"((a)[3]), \
                   "r"(B0), "r"(B1))

// ---------------------------------------------------------------------------
// Prep 1: style s[b,i]
__global__ void prep_s(const float* __restrict__ y,
                       const float* __restrict__ mod_w,
                       const float* __restrict__ mod_b) {
    const int b = blockIdx.x;
    const int i = threadIdx.x;
    const float ms = rsqrtf((float)HID);
    const float4* yr = (const float4*)(y + (size_t)b * HID);
    const float4* wr = (const float4*)(mod_w + (size_t)i * HID);
    float acc = 0.f;
#pragma unroll 8
    for (int h = 0; h < HID / 4; ++h) {
        float4 a = yr[h];
        float4 w = wr[h];
        acc += a.x * w.x + a.y * w.y + a.z * w.z + a.w * w.w;
    }
    g_s[b * CIN + i] = acc * ms + mod_b[i] + 1.0f;
}

// ---------------------------------------------------------------------------
// Prep 2: Winograd weight transform U = G g G^T (fp32, round once to fp16)
__global__ void prep_U(const float* __restrict__ weight) {
    const int o = blockIdx.x;
    const int i = threadIdx.x;
    const float coef = rsqrtf((float)(CIN * 9));
    const float* wp = weight + ((size_t)o * CIN + i) * 9;
    float g[3][3];
    float ss = 0.f;
#pragma unroll
    for (int r = 0; r < 3; ++r)
#pragma unroll
        for (int c = 0; c < 3; ++c) {
            const float v = wp[r * 3 + c] * coef;
            g[r][c] = v;
            ss += v * v;
        }
    g_w2[i * COUT + o] = ss;

    float T[4][3];
#pragma unroll
    for (int c = 0; c < 3; ++c) {
        T[0][c] = g[0][c];
        T[1][c] = 0.5f * (g[0][c] + g[1][c] + g[2][c]);
        T[2][c] = 0.5f * (g[0][c] - g[1][c] + g[2][c]);
        T[3][c] = g[2][c];
    }
    const size_t base = (size_t)o * CIN + i;
#pragma unroll
    for (int r = 0; r < 4; ++r) {
        float u0 = T[r][0];
        float u1 = 0.5f * (T[r][0] + T[r][1] + T[r][2]);
        float u2 = 0.5f * (T[r][0] - T[r][1] + T[r][2]);
        float u3 = T[r][2];
        g_U[(size_t)(r * 4 + 0) * COUT * CIN + base] = __float2half(u0);
        g_U[(size_t)(r * 4 + 1) * COUT * CIN + base] = __float2half(u1);
        g_U[(size_t)(r * 4 + 2) * COUT * CIN + base] = __float2half(u2);
        g_U[(size_t)(r * 4 + 3) * COUT * CIN + base] = __float2half(u3);
    }
}

// ---------------------------------------------------------------------------
// Prep 3: demod d[b,o]
__global__ void prep_d() {
    const int b = blockIdx.x;
    const int o = threadIdx.x;
    __shared__ float s2[CIN];
    for (int i = threadIdx.x; i < CIN; i += blockDim.x) {
        const float s = g_s[b * CIN + i];
        s2[i] = s * s;
    }
    __syncthreads();
    float acc = 0.f;
#pragma unroll 8
    for (int i = 0; i < CIN; ++i)
        acc += g_w2[i * COUT + o] * s2[i];
    g_d[b * COUT + o] = rsqrtf(acc + 1e-8f);
}

// ---------------------------------------------------------------------------
// Input transform: V[coord][ic][b*1024 + ty*32 + tx][ch] = B^T (x) B * s, fp16.
// 16 channels per CTA; halo-only zeroing; contiguous 16ch stores.
// grid (32 ty, 32 ic, 16 b), 256 threads.
__global__ __launch_bounds__(256) void in_tf(const float* __restrict__ x) {
    extern __shared__ __align__(16) char smraw[];
    float* xs = (float*)smraw;                       // [16 i][4 r][72]
    __half* stage = (__half*)(smraw + XS_BYTES);     // [16 c][32 tx][24]

    const int ty = blockIdx.x;
    const int icb = blockIdx.y;
    const int b  = blockIdx.z;
    const int i0 = icb * 16;
    const int tid = threadIdx.x;
    const int lane = tid & 31;
    const int wid = tid >> 5;

    // zero ONLY the halo blocks (slots 0-3 and 68-71; transform reads 3..68)
    if (tid < 128) {
        const int i_l = tid >> 3;
        const int r = (tid >> 1) & 3;
        const int side = tid & 1;          // 0 -> slots 0-3, 1 -> slots 68-71
        *(uint4*)&xs[(i_l * 4 + r) * XS_STRIDE + side * 68] = make_uint4(0, 0, 0, 0);
    }

    // fill interior: in-image rows via cp.async; out-of-image rows zeroed inline
    const int r0 = 2 * ty - 1;
    const uint32_t xs_u = s2u(xs);
#pragma unroll
    for (int k = 0; k < 4; ++k) {
        const int idx = tid + 256 * k;      // (i_l, r, seg)
        const int i_l = idx >> 6;
        const int r = (idx >> 4) & 3;
        const int seg = idx & 15;
        const int row = r0 + r;
        const int off = (i_l * 4 + r) * XS_STRIDE + 4 + seg * 4;
        if ((unsigned)row < HH) {
            const float* src = x + (((size_t)(b * CIN + i0 + i_l)) * HH + row) * WW + seg * 4;
            cp_cg16(xs_u + (uint32_t)(off * 4), src);
        } else {
            *(uint4*)&xs[off] = make_uint4(0, 0, 0, 0);
        }
    }
    cp_commit();
    cp_wait0();
    __syncthreads();

    // transform: thread (channels 2*wid, 2*wid+1; tile tx = lane), scaled by s
    {
        const int tx = lane;
        float tm[2][4][4];
#pragma unroll
        for (int q = 0; q < 2; ++q) {
            const int i_l = 2 * wid + q;
            const float sc = g_s[b * CIN + i0 + i_l];
            const float* base = &xs[(i_l * 4) * XS_STRIDE + 3 + 2 * tx];
            float d[4][4];
#pragma unroll
            for (int r = 0; r < 4; ++r)
#pragma unroll
                for (int c = 0; c < 4; ++c)
                    d[r][c] = base[r * XS_STRIDE + c] * sc;
#pragma unroll
            for (int c = 0; c < 4; ++c) {
                tm[q][0][c] = d[0][c] - d[2][c];
                tm[q][1][c] = d[1][c] + d[2][c];
                tm[q][2][c] = d[2][c] - d[1][c];
                tm[q][3][c] = d[1][c] - d[3][c];
            }
        }
#pragma unroll
        for (int r = 0; r < 4; ++r) {
            float v[2][4];
#pragma unroll
            for (int q = 0; q < 2; ++q) {
                v[q][0] = tm[q][r][0] - tm[q][r][2];
                v[q][1] = tm[q][r][1] + tm[q][r][2];
                v[q][2] = tm[q][r][2] - tm[q][r][1];
                v[q][3] = tm[q][r][1] - tm[q][r][3];
            }
#pragma unroll
            for (int c = 0; c < 4; ++c) {
                *(__half2*)&stage[((r * 4 + c) * 32 + tx) * STG_PAD + 2 * wid] =
                    __floats2half2_rn(v[0][c], v[1][c]);
            }
        }
    }
    __syncthreads();

    // contiguous copy stage -> g_V[coord][icb][tile][16ch]
    const size_t nbase = (size_t)b * 1024 + ty * 32;
#pragma unroll
    for (int k = 0; k < 4; ++k) {
        const int u = tid + 256 * k;        // (c16, tx, j)
        const int j = u & 1;
        const int tx = (u >> 1) & 31;
        const int c16 = u >> 6;
        const uint4* src = (const uint4*)&stage[((size_t)c16 * 32 + tx) * STG_PAD + j * 8];
        uint4* dst = (uint4*)(g_V + ((size_t)(c16 * 32 + icb) * NT + nbase + tx) * 16 + j * 8);
        dst[0] = src[0];
    }
}

// ---------------------------------------------------------------------------
// Winograd GEMM: per coord z, M[o, tile] = sum_i U[z][o][i] V[z][tile][i].
// CTA 128x128, 8 warps (4x2), warp 32x64, fp16 HMMA, 3-stage cp.async.
// grid (o-tiles, n-tiles, z): consecutive bids share the same B tile.
__global__ __launch_bounds__(256, 2)
void wino_gemm() {
    extern __shared__ __align__(128) char sm[];

    const int z  = blockIdx.z;
    const int o0 = blockIdx.x * 128;
    const int n0 = blockIdx.y * 128;
    const int tid = threadIdx.x;
    const int wid = tid >> 5;
    const int lane = tid & 31;
    const int warp_m = wid & 3;
    const int warp_n = wid >> 2;

    const uint32_t sbase = s2u(sm);

    const bool isA = (tid < 128);
    const int r = tid & 127;
    uint32_t dsw[8];
#pragma unroll
    for (int cc = 0; cc < 8; ++cc)
        dsw[cc] = (uint32_t)((isA ? 0 : TILEB) + r * 128 + ((cc ^ (r & 7)) << 4));

    const __half* aRow = g_U + (size_t)z * COUT * CIN + (size_t)(o0 + r) * CIN;
    // B base for (z, tile=n0+r): element (ic, ch) at vBase + ic*NT*16 + ch
    const __half* vBase = g_V + (size_t)z * 32 * NT * 16 + (size_t)(n0 + r) * 16;

    uint32_t offA0[2], offB0[4];
#pragma unroll
    for (int mt = 0; mt < 2; ++mt) {
        const int row = warp_m * 32 + mt * 16 + (lane & 15);
        offA0[mt] = (uint32_t)(row * 128 + (((lane >> 4) ^ (row & 7)) << 4));
    }
#pragma unroll
    for (int q = 0; q < 4; ++q) {
        const int n = warp_n * 64 + q * 16 + (lane & 7) + ((lane >> 4) << 3);
        offB0[q] = (uint32_t)(n * 128 + ((((lane >> 3) & 1) ^ (n & 7)) << 4));
    }

    float acc[2][8][4];
#pragma unroll
    for (int mt = 0; mt < 2; ++mt)
#pragma unroll
        for (int nt = 0; nt < 8; ++nt)
#pragma unroll
            for (int e = 0; e < 4; ++e) acc[mt][nt][e] = 0.f;

    auto issue = [&](int c) {
        const int s = c % NSTAGE;
        const uint32_t base = sbase + (uint32_t)(s * STAGEB);
        if (isA) {
            const __half* src = aRow + c * KC;
#pragma unroll
            for (int cc = 0; cc < 8; ++cc) cp_ca16(base + dsw[cc], src + cc * 8);
        } else {
#pragma unroll
            for (int cc = 0; cc < 8; ++cc) {
                const __half* src = vBase + (size_t)(c * 4 + (cc >> 1)) * (NT * 16)
                                          + (cc & 1) * 8;
                cp_cg16(base + dsw[cc], src);
            }
        }
        cp_commit();
    };

    issue(0);
    issue(1);

    for (int c = 0; c < NCH; ++c) {
        cp_wait1();
        __syncthreads();
        if (c + 2 < NCH) issue(c + 2);
        else cp_commit();

        const uint32_t base = sbase + (uint32_t)((c % NSTAGE) * STAGEB);
        const uint32_t bA = base;
        const uint32_t bB = base + TILEB;

#pragma unroll
        for (int j = 0; j < 4; ++j) {
            const uint32_t jx = (uint32_t)(j << 5);
            uint32_t ah[2][4], bh[4][4];
#pragma unroll
            for (int mt = 0; mt < 2; ++mt) ldsm4(ah[mt], bA + (offA0[mt] ^ jx));
#pragma unroll
            for (int q = 0; q < 4; ++q)   ldsm4(bh[q], bB + (offB0[q] ^ jx));
#pragma unroll
            for (int mt = 0; mt < 2; ++mt)
#pragma unroll
                for (int nt = 0; nt < 8; ++nt) {
                    const int q = nt >> 1;
                    const int e = (nt & 1) * 2;
                    MMA(acc[mt][nt], ah[mt], bh[q][e], bh[q][e + 1]);
                }
        }
    }

    // epilogue: fp16 store to g_M[z][o][n]
    __half* Mb = g_M + (size_t)z * COUT * NT;
#pragma unroll
    for (int mt = 0; mt < 2; ++mt) {
        const int ob = o0 + warp_m * 32 + mt * 16 + (lane >> 2);
        __half* row0 = Mb + (size_t)ob * NT + n0 + warp_n * 64;
        __half* row1 = row0 + (size_t)8 * NT;
#pragma unroll
        for (int nt = 0; nt < 8; ++nt) {
            const int w = nt * 8 + (lane & 3) * 2;
            *(__half2*)(row0 + w) = __floats2half2_rn(acc[mt][nt][0], acc[mt][nt][1]);
            *(__half2*)(row1 + w) = __floats2half2_rn(acc[mt][nt][2], acc[mt][nt][3]);
        }
    }
}

// ---------------------------------------------------------------------------
// Output transform: Y = A^T M A, demod/bias/noise, DIRECT coalesced stores
// (tile-pair results are already contiguous float4 in NCHW; no smem plane).
__global__ __launch_bounds__(256) void out_tf(const float* __restrict__ noise,
                                              const float* __restrict__ bias,
                                              const float* __restrict__ noise_scale,
                                              float* __restrict__ out) {
    const int o = blockIdx.x;
    const int b = blockIdx.y;
    const int tid = threadIdx.x;

    const float dd = g_d[b * COUT + o];
    const float bb = bias[o];
    const float ns = noise_scale[0];
    const float* nzb = noise + (size_t)b * 4096;
    float* outb = out + ((size_t)(b * COUT + o)) * 4096;

    const size_t mi0 = (size_t)o * NT + (size_t)b * 1024;
#pragma unroll
    for (int q = 0; q < 2; ++q) {
        const int pr = q * 256 + tid;       // pair index 0..511
        const int t0 = pr * 2;              // even tile
        float2 m[16];
#pragma unroll
        for (int c = 0; c < 16; ++c)
            m[c] = __half22float2(*(const __half2*)(g_M + (size_t)c * COUT * NT + mi0 + t0));
        float2 t0r[4], t1r[4];
#pragma unroll
        for (int c = 0; c < 4; ++c) {
            t0r[c].x = m[0 + c].x + m[4 + c].x + m[8 + c].x;
            t0r[c].y = m[0 + c].y + m[4 + c].y + m[8 + c].y;
            t1r[c].x = m[4 + c].x - m[8 + c].x - m[12 + c].x;
            t1r[c].y = m[4 + c].y - m[8 + c].y - m[12 + c].y;
        }
        const int tyy = t0 >> 5;
        const int col = 2 * (t0 & 31);      // multiple of 4
        float4 rowa, rowb;
        rowa.x = t0r[0].x + t0r[1].x + t0r[2].x;
        rowa.y = t0r[1].x - t0r[2].x - t0r[3].x;
        rowa.z = t0r[0].y + t0r[1].y + t0r[2].y;
        rowa.w = t0r[1].y - t0r[2].y - t0r[3].y;
        rowb.x = t1r[0].x + t1r[1].x + t1r[2].x;
        rowb.y = t1r[1].x - t1r[2].x - t1r[3].x;
        rowb.z = t1r[0].y + t1r[1].y + t1r[2].y;
        rowb.w = t1r[1].y - t1r[2].y - t1r[3].y;

        const int pa = (2 * tyy) * 64 + col;
        const int pb = (2 * tyy + 1) * 64 + col;
        const float4 nza = *(const float4*)(nzb + pa);
        const float4 nzbv = *(const float4*)(nzb + pb);
        float4 ra, rb;
        ra.x = rowa.x * dd + nza.x * ns + bb;
        ra.y = rowa.y * dd + nza.y * ns + bb;
        ra.z = rowa.z * dd + nza.z * ns + bb;
        ra.w = rowa.w * dd + nza.w * ns + bb;
        rb.x = rowb.x * dd + nzbv.x * ns + bb;
        rb.y = rowb.y * dd + nzbv.y * ns + bb;
        rb.z = rowb.z * dd + nzbv.z * ns + bb;
        rb.w = rowb.w * dd + nzbv.w * ns + bb;
        *(float4*)(outb + pa) = ra;
        *(float4*)(outb + pb) = rb;
    }
}

// ---------------------------------------------------------------------------
extern "C" void kernel_launch(void* const* d_in, const int* in_sizes, int n_in,
                              void* d_out, int out_size) {
    const float* x           = (const float*)d_in[0];
    const float* y           = (const float*)d_in[1];
    const float* noise       = (const float*)d_in[2];
    const float* weight      = (const float*)d_in[3];
    const float* bias        = (const float*)d_in[4];
    const float* mod_w       = (const float*)d_in[5];
    const float* mod_b       = (const float*)d_in[6];
    const float* noise_scale = (const float*)d_in[7];
    float* out = (float*)d_out;

    cudaFuncSetAttribute(wino_gemm, cudaFuncAttributeMaxDynamicSharedMemorySize, DYN_GEMM);
    cudaFuncSetAttribute(in_tf, cudaFuncAttributeMaxDynamicSharedMemorySize, DYN_INTF);

    prep_s<<<NB, CIN>>>(y, mod_w, mod_b);
    prep_U<<<COUT, CIN>>>(weight);
    prep_d<<<NB, COUT>>>();
    in_tf<<<dim3(32, 32, NB), 256, DYN_INTF>>>(x);
    wino_gemm<<<dim3(COUT / 128, NT / 128, 16), 256, DYN_GEMM>>>();
    out_tf<<<dim3(COUT, NB), 256>>>(noise, bias, noise_scale, out);
}

// round 15
// speedup vs baseline: 1.0050x; 1.0050x over previous
#include <cuda_runtime.h>
#include <cuda_fp16.h>
#include <cstdint>

#define NB   16
#define CIN  512
#define COUT 512
#define HID  512
#define HH   64
#define WW   64
#define NT   16384                 // 16 batches x 32x32 output tiles

// GEMM tiling (per Winograd coordinate): M=COUT, N=NT, K=CIN
#define KC     64
#define NCH    (CIN / KC)          // 8
#define TILEB  (128 * KC * 2)      // 16384 B
#define STAGEB (2 * TILEB)
#define NSTAGE 3
#define DYN_GEMM (NSTAGE * STAGEB) // 96 KB

// in_tf: 16 channels per CTA, paired-channel half2 stage writes
#define XS_STRIDE 72               // floats per row: [3 pad][w=-1..64][3 pad]
#define XS_BYTES  (16 * 4 * XS_STRIDE * 4)        // 18432
#define STG_PAD   24               // halfs per stage row (16 + 8 pad, 48B)
#define STG_BYTES (16 * 32 * STG_PAD * 2)         // 24576
#define DYN_INTF  (XS_BYTES + STG_BYTES)          // 43008

// ---------------- static device scratch -------------------------------------
__device__ float g_s[NB * CIN];
__device__ float g_d[NB * COUT];
__device__ float g_w2[CIN * COUT];
__device__ __half g_U[(size_t)16 * COUT * CIN];   // [coord][o][i]
__device__ __half g_V[(size_t)16 * 32 * NT * 16]; // [coord][ic16][tile][16ch]
__device__ __half g_M[(size_t)16 * COUT * NT];    // [coord][o][tile], fp16

// ---------------- helpers ----------------------------------------------------
__device__ __forceinline__ uint32_t s2u(const void* p) {
    uint32_t a;
    asm("{ .reg .u64 t; cvta.to.shared.u64 t, %1; cvt.u32.u64 %0, t; }" : "=r"(a) : "l"(p));
    return a;
}
__device__ __forceinline__ void cp_ca16(uint32_t dst, const void* src) {
    asm volatile("cp.async.ca.shared.global [%0], [%1], 16;"
                 :: "r"(dst), "l"(src) : "memory");
}
__device__ __forceinline__ void cp_cg16(uint32_t dst, const void* src) {
    asm volatile("cp.async.cg.shared.global [%0], [%1], 16;"
                 :: "r"(dst), "l"(src) : "memory");
}
__device__ __forceinline__ void cp_commit() {
    asm volatile("cp.async.commit_group;" ::: "memory");
}
__device__ __forceinline__ void cp_wait1() {
    asm volatile("cp.async.wait_group 1;" ::: "memory");
}
__device__ __forceinline__ void cp_wait0() {
    asm volatile("cp.async.wait_group 0;" ::: "memory");
}
__device__ __forceinline__ void ldsm4(uint32_t* r, uint32_t addr) {
    asm volatile("ldmatrix.sync.aligned.m8n8.x4.shared.b16 {%0,%1,%2,%3}, [%4];"
                 : "=r"(r[0]), "=r"(r[1]), "=r"(r[2]), "=r"(r[3]) : "r"(addr));
}
#define MMA(c, a, B0, B1) \
    asm volatile("mma.sync.aligned.m16n8k16.row.col.f32.f16.f16.f32 " \
                 "{%0,%1,%2,%3},{%4,%5,%6,%7},{%8,%9},{%0,%1,%2,%3};" \
                 : "+f"((c)[0]), "+f"((c)[1]), "+f"((c)[2]), "+f"((c)[3]) \
                 : "r"((a)[0]), "r"((a)[1]), "r"((a)[2]), "r"((a)[3]), \
                   "r"(B0), "r"(B1))

// ---------------------------------------------------------------------------
// Prep 1: style s[b,i]
__global__ void prep_s(const float* __restrict__ y,
                       const float* __restrict__ mod_w,
                       const float* __restrict__ mod_b) {
    const int b = blockIdx.x;
    const int i = threadIdx.x;
    const float ms = rsqrtf((float)HID);
    const float4* yr = (const float4*)(y + (size_t)b * HID);
    const float4* wr = (const float4*)(mod_w + (size_t)i * HID);
    float acc = 0.f;
#pragma unroll 8
    for (int h = 0; h < HID / 4; ++h) {
        float4 a = yr[h];
        float4 w = wr[h];
        acc += a.x * w.x + a.y * w.y + a.z * w.z + a.w * w.w;
    }
    g_s[b * CIN + i] = acc * ms + mod_b[i] + 1.0f;
}

// ---------------------------------------------------------------------------
// Prep 2: Winograd weight transform U = G g G^T (fp32, round once to fp16)
__global__ void prep_U(const float* __restrict__ weight) {
    const int o = blockIdx.x;
    const int i = threadIdx.x;
    const float coef = rsqrtf((float)(CIN * 9));
    const float* wp = weight + ((size_t)o * CIN + i) * 9;
    float g[3][3];
    float ss = 0.f;
#pragma unroll
    for (int r = 0; r < 3; ++r)
#pragma unroll
        for (int c = 0; c < 3; ++c) {
            const float v = wp[r * 3 + c] * coef;
            g[r][c] = v;
            ss += v * v;
        }
    g_w2[i * COUT + o] = ss;

    float T[4][3];
#pragma unroll
    for (int c = 0; c < 3; ++c) {
        T[0][c] = g[0][c];
        T[1][c] = 0.5f * (g[0][c] + g[1][c] + g[2][c]);
        T[2][c] = 0.5f * (g[0][c] - g[1][c] + g[2][c]);
        T[3][c] = g[2][c];
    }
    const size_t base = (size_t)o * CIN + i;
#pragma unroll
    for (int r = 0; r < 4; ++r) {
        float u0 = T[r][0];
        float u1 = 0.5f * (T[r][0] + T[r][1] + T[r][2]);
        float u2 = 0.5f * (T[r][0] - T[r][1] + T[r][2]);
        float u3 = T[r][2];
        g_U[(size_t)(r * 4 + 0) * COUT * CIN + base] = __float2half(u0);
        g_U[(size_t)(r * 4 + 1) * COUT * CIN + base] = __float2half(u1);
        g_U[(size_t)(r * 4 + 2) * COUT * CIN + base] = __float2half(u2);
        g_U[(size_t)(r * 4 + 3) * COUT * CIN + base] = __float2half(u3);
    }
}

// ---------------------------------------------------------------------------
// Prep 3: demod d[b,o]
__global__ void prep_d() {
    const int b = blockIdx.x;
    const int o = threadIdx.x;
    __shared__ float s2[CIN];
    for (int i = threadIdx.x; i < CIN; i += blockDim.x) {
        const float s = g_s[b * CIN + i];
        s2[i] = s * s;
    }
    __syncthreads();
    float acc = 0.f;
#pragma unroll 8
    for (int i = 0; i < CIN; ++i)
        acc += g_w2[i * COUT + o] * s2[i];
    g_d[b * COUT + o] = rsqrtf(acc + 1e-8f);
}

// ---------------------------------------------------------------------------
// Input transform: V[coord][ic][b*1024 + ty*32 + tx][ch] = B^T (x) B * s, fp16.
// 16 channels per CTA; halo-only zeroing; contiguous 16ch stores.
// grid (32 ty, 32 ic, 16 b), 256 threads.
__global__ __launch_bounds__(256) void in_tf(const float* __restrict__ x) {
    extern __shared__ __align__(16) char smraw[];
    float* xs = (float*)smraw;                       // [16 i][4 r][72]
    __half* stage = (__half*)(smraw + XS_BYTES);     // [16 c][32 tx][24]

    const int ty = blockIdx.x;
    const int icb = blockIdx.y;
    const int b  = blockIdx.z;
    const int i0 = icb * 16;
    const int tid = threadIdx.x;
    const int lane = tid & 31;
    const int wid = tid >> 5;

    // zero ONLY the halo blocks (slots 0-3 and 68-71; transform reads 3..68)
    if (tid < 128) {
        const int i_l = tid >> 3;
        const int r = (tid >> 1) & 3;
        const int side = tid & 1;          // 0 -> slots 0-3, 1 -> slots 68-71
        *(uint4*)&xs[(i_l * 4 + r) * XS_STRIDE + side * 68] = make_uint4(0, 0, 0, 0);
    }

    // fill interior: in-image rows via cp.async; out-of-image rows zeroed inline
    const int r0 = 2 * ty - 1;
    const uint32_t xs_u = s2u(xs);
#pragma unroll
    for (int k = 0; k < 4; ++k) {
        const int idx = tid + 256 * k;      // (i_l, r, seg)
        const int i_l = idx >> 6;
        const int r = (idx >> 4) & 3;
        const int seg = idx & 15;
        const int row = r0 + r;
        const int off = (i_l * 4 + r) * XS_STRIDE + 4 + seg * 4;
        if ((unsigned)row < HH) {
            const float* src = x + (((size_t)(b * CIN + i0 + i_l)) * HH + row) * WW + seg * 4;
            cp_cg16(xs_u + (uint32_t)(off * 4), src);
        } else {
            *(uint4*)&xs[off] = make_uint4(0, 0, 0, 0);
        }
    }
    cp_commit();
    cp_wait0();
    __syncthreads();

    // transform: thread (channels 2*wid, 2*wid+1; tile tx = lane), scaled by s
    {
        const int tx = lane;
        float tm[2][4][4];
#pragma unroll
        for (int q = 0; q < 2; ++q) {
            const int i_l = 2 * wid + q;
            const float sc = g_s[b * CIN + i0 + i_l];
            const float* base = &xs[(i_l * 4) * XS_STRIDE + 3 + 2 * tx];
            float d[4][4];
#pragma unroll
            for (int r = 0; r < 4; ++r)
#pragma unroll
                for (int c = 0; c < 4; ++c)
                    d[r][c] = base[r * XS_STRIDE + c] * sc;
#pragma unroll
            for (int c = 0; c < 4; ++c) {
                tm[q][0][c] = d[0][c] - d[2][c];
                tm[q][1][c] = d[1][c] + d[2][c];
                tm[q][2][c] = d[2][c] - d[1][c];
                tm[q][3][c] = d[1][c] - d[3][c];
            }
        }
#pragma unroll
        for (int r = 0; r < 4; ++r) {
            float v[2][4];
#pragma unroll
            for (int q = 0; q < 2; ++q) {
                v[q][0] = tm[q][r][0] - tm[q][r][2];
                v[q][1] = tm[q][r][1] + tm[q][r][2];
                v[q][2] = tm[q][r][2] - tm[q][r][1];
                v[q][3] = tm[q][r][1] - tm[q][r][3];
            }
#pragma unroll
            for (int c = 0; c < 4; ++c) {
                *(__half2*)&stage[((r * 4 + c) * 32 + tx) * STG_PAD + 2 * wid] =
                    __floats2half2_rn(v[0][c], v[1][c]);
            }
        }
    }
    __syncthreads();

    // contiguous copy stage -> g_V[coord][icb][tile][16ch]
    const size_t nbase = (size_t)b * 1024 + ty * 32;
#pragma unroll
    for (int k = 0; k < 4; ++k) {
        const int u = tid + 256 * k;        // (c16, tx, j)
        const int j = u & 1;
        const int tx = (u >> 1) & 31;
        const int c16 = u >> 6;
        const uint4* src = (const uint4*)&stage[((size_t)c16 * 32 + tx) * STG_PAD + j * 8];
        uint4* dst = (uint4*)(g_V + ((size_t)(c16 * 32 + icb) * NT + nbase + tx) * 16 + j * 8);
        dst[0] = src[0];
    }
}

// ---------------------------------------------------------------------------
// Winograd GEMM: per coord z, M[o, tile] = sum_i U[z][o][i] V[z][tile][i].
// CTA 128x128, 8 warps (4x2), warp 32x64, fp16 HMMA, 3-stage cp.async.
// grid (n-tiles, o-tiles, z): 128-CTA window shares the same A (U) slab.
__global__ __launch_bounds__(256, 2)
void wino_gemm() {
    extern __shared__ __align__(128) char sm[];

    const int z  = blockIdx.z;
    const int o0 = blockIdx.y * 128;
    const int n0 = blockIdx.x * 128;
    const int tid = threadIdx.x;
    const int wid = tid >> 5;
    const int lane = tid & 31;
    const int warp_m = wid & 3;
    const int warp_n = wid >> 2;

    const uint32_t sbase = s2u(sm);

    const bool isA = (tid < 128);
    const int r = tid & 127;
    uint32_t dsw[8];
#pragma unroll
    for (int cc = 0; cc < 8; ++cc)
        dsw[cc] = (uint32_t)((isA ? 0 : TILEB) + r * 128 + ((cc ^ (r & 7)) << 4));

    const __half* aRow = g_U + (size_t)z * COUT * CIN + (size_t)(o0 + r) * CIN;
    // B base for (z, tile=n0+r): element (ic, ch) at vBase + ic*NT*16 + ch
    const __half* vBase = g_V + (size_t)z * 32 * NT * 16 + (size_t)(n0 + r) * 16;

    uint32_t offA0[2], offB0[4];
#pragma unroll
    for (int mt = 0; mt < 2; ++mt) {
        const int row = warp_m * 32 + mt * 16 + (lane & 15);
        offA0[mt] = (uint32_t)(row * 128 + (((lane >> 4) ^ (row & 7)) << 4));
    }
#pragma unroll
    for (int q = 0; q < 4; ++q) {
        const int n = warp_n * 64 + q * 16 + (lane & 7) + ((lane >> 4) << 3);
        offB0[q] = (uint32_t)(n * 128 + ((((lane >> 3) & 1) ^ (n & 7)) << 4));
    }

    float acc[2][8][4];
#pragma unroll
    for (int mt = 0; mt < 2; ++mt)
#pragma unroll
        for (int nt = 0; nt < 8; ++nt)
#pragma unroll
            for (int e = 0; e < 4; ++e) acc[mt][nt][e] = 0.f;

    auto issue = [&](int c) {
        const int s = c % NSTAGE;
        const uint32_t base = sbase + (uint32_t)(s * STAGEB);
        if (isA) {
            const __half* src = aRow + c * KC;
#pragma unroll
            for (int cc = 0; cc < 8; ++cc) cp_ca16(base + dsw[cc], src + cc * 8);
        } else {
#pragma unroll
            for (int cc = 0; cc < 8; ++cc) {
                const __half* src = vBase + (size_t)(c * 4 + (cc >> 1)) * (NT * 16)
                                          + (cc & 1) * 8;
                cp_cg16(base + dsw[cc], src);
            }
        }
        cp_commit();
    };

    issue(0);
    issue(1);

    for (int c = 0; c < NCH; ++c) {
        cp_wait1();
        __syncthreads();
        if (c + 2 < NCH) issue(c + 2);
        else cp_commit();

        const uint32_t base = sbase + (uint32_t)((c % NSTAGE) * STAGEB);
        const uint32_t bA = base;
        const uint32_t bB = base + TILEB;

#pragma unroll
        for (int j = 0; j < 4; ++j) {
            const uint32_t jx = (uint32_t)(j << 5);
            uint32_t ah[2][4], bh[4][4];
#pragma unroll
            for (int mt = 0; mt < 2; ++mt) ldsm4(ah[mt], bA + (offA0[mt] ^ jx));
#pragma unroll
            for (int q = 0; q < 4; ++q)   ldsm4(bh[q], bB + (offB0[q] ^ jx));
#pragma unroll
            for (int mt = 0; mt < 2; ++mt)
#pragma unroll
                for (int nt = 0; nt < 8; ++nt) {
                    const int q = nt >> 1;
                    const int e = (nt & 1) * 2;
                    MMA(acc[mt][nt], ah[mt], bh[q][e], bh[q][e + 1]);
                }
        }
    }

    // epilogue: fp16 store to g_M[z][o][n]
    __half* Mb = g_M + (size_t)z * COUT * NT;
#pragma unroll
    for (int mt = 0; mt < 2; ++mt) {
        const int ob = o0 + warp_m * 32 + mt * 16 + (lane >> 2);
        __half* row0 = Mb + (size_t)ob * NT + n0 + warp_n * 64;
        __half* row1 = row0 + (size_t)8 * NT;
#pragma unroll
        for (int nt = 0; nt < 8; ++nt) {
            const int w = nt * 8 + (lane & 3) * 2;
            *(__half2*)(row0 + w) = __floats2half2_rn(acc[mt][nt][0], acc[mt][nt][1]);
            *(__half2*)(row1 + w) = __floats2half2_rn(acc[mt][nt][2], acc[mt][nt][3]);
        }
    }
}

// ---------------------------------------------------------------------------
// Output transform: Y = A^T M A, demod/bias/noise, DIRECT coalesced stores
// (tile-pair results are already contiguous float4 in NCHW; no smem plane).
__global__ __launch_bounds__(256) void out_tf(const float* __restrict__ noise,
                                              const float* __restrict__ bias,
                                              const float* __restrict__ noise_scale,
                                              float* __restrict__ out) {
    const int o = blockIdx.x;
    const int b = blockIdx.y;
    const int tid = threadIdx.x;

    const float dd = g_d[b * COUT + o];
    const float bb = bias[o];
    const float ns = noise_scale[0];
    const float* nzb = noise + (size_t)b * 4096;
    float* outb = out + ((size_t)(b * COUT + o)) * 4096;

    const size_t mi0 = (size_t)o * NT + (size_t)b * 1024;
#pragma unroll
    for (int q = 0; q < 2; ++q) {
        const int pr = q * 256 + tid;       // pair index 0..511
        const int t0 = pr * 2;              // even tile
        float2 m[16];
#pragma unroll
        for (int c = 0; c < 16; ++c)
            m[c] = __half22float2(*(const __half2*)(g_M + (size_t)c * COUT * NT + mi0 + t0));
        float2 t0r[4], t1r[4];
#pragma unroll
        for (int c = 0; c < 4; ++c) {
            t0r[c].x = m[0 + c].x + m[4 + c].x + m[8 + c].x;
            t0r[c].y = m[0 + c].y + m[4 + c].y + m[8 + c].y;
            t1r[c].x = m[4 + c].x - m[8 + c].x - m[12 + c].x;
            t1r[c].y = m[4 + c].y - m[8 + c].y - m[12 + c].y;
        }
        const int tyy = t0 >> 5;
        const int col = 2 * (t0 & 31);      // multiple of 4
        float4 rowa, rowb;
        rowa.x = t0r[0].x + t0r[1].x + t0r[2].x;
        rowa.y = t0r[1].x - t0r[2].x - t0r[3].x;
        rowa.z = t0r[0].y + t0r[1].y + t0r[2].y;
        rowa.w = t0r[1].y - t0r[2].y - t0r[3].y;
        rowb.x = t1r[0].x + t1r[1].x + t1r[2].x;
        rowb.y = t1r[1].x - t1r[2].x - t1r[3].x;
        rowb.z = t1r[0].y + t1r[1].y + t1r[2].y;
        rowb.w = t1r[1].y - t1r[2].y - t1r[3].y;

        const int pa = (2 * tyy) * 64 + col;
        const int pb = (2 * tyy + 1) * 64 + col;
        const float4 nza = *(const float4*)(nzb + pa);
        const float4 nzbv = *(const float4*)(nzb + pb);
        float4 ra, rb;
        ra.x = rowa.x * dd + nza.x * ns + bb;
        ra.y = rowa.y * dd + nza.y * ns + bb;
        ra.z = rowa.z * dd + nza.z * ns + bb;
        ra.w = rowa.w * dd + nza.w * ns + bb;
        rb.x = rowb.x * dd + nzbv.x * ns + bb;
        rb.y = rowb.y * dd + nzbv.y * ns + bb;
        rb.z = rowb.z * dd + nzbv.z * ns + bb;
        rb.w = rowb.w * dd + nzbv.w * ns + bb;
        *(float4*)(outb + pa) = ra;
        *(float4*)(outb + pb) = rb;
    }
}

// ---------------------------------------------------------------------------
extern "C" void kernel_launch(void* const* d_in, const int* in_sizes, int n_in,
                              void* d_out, int out_size) {
    const float* x           = (const float*)d_in[0];
    const float* y           = (const float*)d_in[1];
    const float* noise       = (const float*)d_in[2];
    const float* weight      = (const float*)d_in[3];
    const float* bias        = (const float*)d_in[4];
    const float* mod_w       = (const float*)d_in[5];
    const float* mod_b       = (const float*)d_in[6];
    const float* noise_scale = (const float*)d_in[7];
    float* out = (float*)d_out;

    cudaFuncSetAttribute(wino_gemm, cudaFuncAttributeMaxDynamicSharedMemorySize, DYN_GEMM);
    cudaFuncSetAttribute(in_tf, cudaFuncAttributeMaxDynamicSharedMemorySize, DYN_INTF);

    prep_s<<<NB, CIN>>>(y, mod_w, mod_b);
    prep_U<<<COUT, CIN>>>(weight);
    prep_d<<<NB, COUT>>>();
    in_tf<<<dim3(32, 32, NB), 256, DYN_INTF>>>(x);
    wino_gemm<<<dim3(NT / 128, COUT / 128, 16), 256, DYN_GEMM>>>();
    out_tf<<<dim3(COUT, NB), 256>>>(noise, bias, noise_scale, out);
}

// round 16
// speedup vs baseline: 1.0283x; 1.0232x over previous
#include <cuda_runtime.h>
#include <cuda_fp16.h>
#include <cstdint>

#define NB   16
#define CIN  512
#define COUT 512
#define HID  512
#define HH   64
#define WW   64
#define NT   16384                 // 16 batches x 32x32 output tiles

// GEMM tiling (per Winograd coordinate): M=COUT, N=NT, K=CIN
#define KC     64
#define NCH    (CIN / KC)          // 8
#define TILEB  (128 * KC * 2)      // 16384 B
#define STAGEB (2 * TILEB)
#define NSTAGE 3
#define DYN_GEMM (NSTAGE * STAGEB) // 96 KB

// in_tf: 16 channels x 2 tile-rows per CTA (6 input rows, 25% fewer reads)
#define XS_STRIDE 72               // floats per row: [3 pad][w=-1..64][3 pad]
#define XS_BYTES  (16 * 6 * XS_STRIDE * 4)        // 27648
#define STG_PAD   24               // halfs per stage row (16 + 8 pad, 48B)
#define STG_BYTES (16 * 32 * STG_PAD * 2)         // 24576
#define DYN_INTF  (XS_BYTES + STG_BYTES)          // 52224

// ---------------- static device scratch -------------------------------------
__device__ float g_s[NB * CIN];
__device__ float g_d[NB * COUT];
__device__ float g_w2[CIN * COUT];
__device__ __half g_U[(size_t)16 * COUT * CIN];   // [coord][o][i]
__device__ __half g_V[(size_t)16 * 32 * NT * 16]; // [coord][ic16][tile][16ch]
__device__ __half g_M[(size_t)16 * COUT * NT];    // [coord][o][tile], fp16

// ---------------- helpers ----------------------------------------------------
__device__ __forceinline__ uint32_t s2u(const void* p) {
    uint32_t a;
    asm("{ .reg .u64 t; cvta.to.shared.u64 t, %1; cvt.u32.u64 %0, t; }" : "=r"(a) : "l"(p));
    return a;
}
__device__ __forceinline__ void cp_ca16(uint32_t dst, const void* src) {
    asm volatile("cp.async.ca.shared.global [%0], [%1], 16;"
                 :: "r"(dst), "l"(src) : "memory");
}
__device__ __forceinline__ void cp_cg16(uint32_t dst, const void* src) {
    asm volatile("cp.async.cg.shared.global [%0], [%1], 16;"
                 :: "r"(dst), "l"(src) : "memory");
}
__device__ __forceinline__ void cp_commit() {
    asm volatile("cp.async.commit_group;" ::: "memory");
}
__device__ __forceinline__ void cp_wait1() {
    asm volatile("cp.async.wait_group 1;" ::: "memory");
}
__device__ __forceinline__ void cp_wait0() {
    asm volatile("cp.async.wait_group 0;" ::: "memory");
}
__device__ __forceinline__ void ldsm4(uint32_t* r, uint32_t addr) {
    asm volatile("ldmatrix.sync.aligned.m8n8.x4.shared.b16 {%0,%1,%2,%3}, [%4];"
                 : "=r"(r[0]), "=r"(r[1]), "=r"(r[2]), "=r"(r[3]) : "r"(addr));
}
#define MMA(c, a, B0, B1) \
    asm volatile("mma.sync.aligned.m16n8k16.row.col.f32.f16.f16.f32 " \
                 "{%0,%1,%2,%3},{%4,%5,%6,%7},{%8,%9},{%0,%1,%2,%3};" \
                 : "+f"((c)[0]), "+f"((c)[1]), "+f"((c)[2]), "+f"((c)[3]) \
                 : "r"((a)[0]), "r"((a)[1]), "r"((a)[2]), "r"((a)[3]), \
                   "r"(B0), "r"(B1))

// ---------------------------------------------------------------------------
// Prep 1+2 merged: blocks 0..NB-1 do style s[b,i]; blocks NB.. do U transform.
__global__ void prep_su(const float* __restrict__ y,
                        const float* __restrict__ mod_w,
                        const float* __restrict__ mod_b,
                        const float* __restrict__ weight) {
    if (blockIdx.x < NB) {
        const int b = blockIdx.x;
        const int i = threadIdx.x;
        const float ms = rsqrtf((float)HID);
        const float4* yr = (const float4*)(y + (size_t)b * HID);
        const float4* wr = (const float4*)(mod_w + (size_t)i * HID);
        float acc = 0.f;
#pragma unroll 8
        for (int h = 0; h < HID / 4; ++h) {
            float4 a = yr[h];
            float4 w = wr[h];
            acc += a.x * w.x + a.y * w.y + a.z * w.z + a.w * w.w;
        }
        g_s[b * CIN + i] = acc * ms + mod_b[i] + 1.0f;
    } else {
        const int o = blockIdx.x - NB;
        const int i = threadIdx.x;
        const float coef = rsqrtf((float)(CIN * 9));
        const float* wp = weight + ((size_t)o * CIN + i) * 9;
        float g[3][3];
        float ss = 0.f;
#pragma unroll
        for (int r = 0; r < 3; ++r)
#pragma unroll
            for (int c = 0; c < 3; ++c) {
                const float v = wp[r * 3 + c] * coef;
                g[r][c] = v;
                ss += v * v;
            }
        g_w2[i * COUT + o] = ss;

        float T[4][3];
#pragma unroll
        for (int c = 0; c < 3; ++c) {
            T[0][c] = g[0][c];
            T[1][c] = 0.5f * (g[0][c] + g[1][c] + g[2][c]);
            T[2][c] = 0.5f * (g[0][c] - g[1][c] + g[2][c]);
            T[3][c] = g[2][c];
        }
        const size_t base = (size_t)o * CIN + i;
#pragma unroll
        for (int r = 0; r < 4; ++r) {
            float u0 = T[r][0];
            float u1 = 0.5f * (T[r][0] + T[r][1] + T[r][2]);
            float u2 = 0.5f * (T[r][0] - T[r][1] + T[r][2]);
            float u3 = T[r][2];
            g_U[(size_t)(r * 4 + 0) * COUT * CIN + base] = __float2half(u0);
            g_U[(size_t)(r * 4 + 1) * COUT * CIN + base] = __float2half(u1);
            g_U[(size_t)(r * 4 + 2) * COUT * CIN + base] = __float2half(u2);
            g_U[(size_t)(r * 4 + 3) * COUT * CIN + base] = __float2half(u3);
        }
    }
}

// ---------------------------------------------------------------------------
// Prep 3: demod d[b,o]
__global__ void prep_d() {
    const int b = blockIdx.x;
    const int o = threadIdx.x;
    __shared__ float s2[CIN];
    for (int i = threadIdx.x; i < CIN; i += blockDim.x) {
        const float s = g_s[b * CIN + i];
        s2[i] = s * s;
    }
    __syncthreads();
    float acc = 0.f;
#pragma unroll 8
    for (int i = 0; i < CIN; ++i)
        acc += g_w2[i * COUT + o] * s2[i];
    g_d[b * COUT + o] = rsqrtf(acc + 1e-8f);
}

// ---------------------------------------------------------------------------
// Input transform: V[coord][ic][b*1024 + ty*32 + tx][ch] = B^T (x) B * s, fp16.
// 16 channels x 2 tile-rows per CTA: 6 input rows loaded once (25% fewer
// reads), two transform+store passes reuse the stage buffer.
// grid (16 typ, 32 ic, 16 b), 256 threads.
__global__ __launch_bounds__(256) void in_tf(const float* __restrict__ x) {
    extern __shared__ __align__(16) char smraw[];
    float* xs = (float*)smraw;                       // [16 i][6 r][72]
    __half* stage = (__half*)(smraw + XS_BYTES);     // [16 c][32 tx][24]

    const int typ = blockIdx.x;                      // pair of tile-rows
    const int icb = blockIdx.y;
    const int b  = blockIdx.z;
    const int i0 = icb * 16;
    const int tid = threadIdx.x;
    const int lane = tid & 31;
    const int wid = tid >> 5;

    // zero ONLY the halo blocks (slots 0-3 and 68-71; transform reads 3..68)
    if (tid < 192) {
        const int i_l = tid / 12;
        const int rem = tid - i_l * 12;
        const int r = rem >> 1;
        const int side = rem & 1;          // 0 -> slots 0-3, 1 -> slots 68-71
        *(uint4*)&xs[(i_l * 6 + r) * XS_STRIDE + side * 68] = make_uint4(0, 0, 0, 0);
    }

    // fill interior: 6 rows per channel (rows 4*typ-1 .. 4*typ+4)
    const int r0 = 4 * typ - 1;
    const uint32_t xs_u = s2u(xs);
#pragma unroll
    for (int k = 0; k < 6; ++k) {
        const int idx = tid + 256 * k;      // (i_l, r, seg), 16*6*16 = 1536
        const int i_l = idx / 96;
        const int rem = idx - i_l * 96;
        const int r = rem >> 4;
        const int seg = rem & 15;
        const int row = r0 + r;
        const int off = (i_l * 6 + r) * XS_STRIDE + 4 + seg * 4;
        if ((unsigned)row < HH) {
            const float* src = x + (((size_t)(b * CIN + i0 + i_l)) * HH + row) * WW + seg * 4;
            cp_cg16(xs_u + (uint32_t)(off * 4), src);
        } else {
            *(uint4*)&xs[off] = make_uint4(0, 0, 0, 0);
        }
    }
    cp_commit();
    cp_wait0();
    __syncthreads();

    // two sub-tiles (ty = 2*typ + sub); stage buffer reused
#pragma unroll 1
    for (int sub = 0; sub < 2; ++sub) {
        const int tx = lane;
        float tm[2][4][4];
#pragma unroll
        for (int q = 0; q < 2; ++q) {
            const int i_l = 2 * wid + q;
            const float sc = g_s[b * CIN + i0 + i_l];
            const float* base = &xs[(i_l * 6 + sub * 2) * XS_STRIDE + 3 + 2 * tx];
            float d[4][4];
#pragma unroll
            for (int r = 0; r < 4; ++r)
#pragma unroll
                for (int c = 0; c < 4; ++c)
                    d[r][c] = base[r * XS_STRIDE + c] * sc;
#pragma unroll
            for (int c = 0; c < 4; ++c) {
                tm[q][0][c] = d[0][c] - d[2][c];
                tm[q][1][c] = d[1][c] + d[2][c];
                tm[q][2][c] = d[2][c] - d[1][c];
                tm[q][3][c] = d[1][c] - d[3][c];
            }
        }
#pragma unroll
        for (int r = 0; r < 4; ++r) {
            float v[2][4];
#pragma unroll
            for (int q = 0; q < 2; ++q) {
                v[q][0] = tm[q][r][0] - tm[q][r][2];
                v[q][1] = tm[q][r][1] + tm[q][r][2];
                v[q][2] = tm[q][r][2] - tm[q][r][1];
                v[q][3] = tm[q][r][1] - tm[q][r][3];
            }
#pragma unroll
            for (int c = 0; c < 4; ++c) {
                *(__half2*)&stage[((r * 4 + c) * 32 + tx) * STG_PAD + 2 * wid] =
                    __floats2half2_rn(v[0][c], v[1][c]);
            }
        }
        __syncthreads();

        // contiguous copy stage -> g_V[coord][icb][tile][16ch]
        const size_t nbase = (size_t)b * 1024 + (2 * typ + sub) * 32;
#pragma unroll
        for (int k = 0; k < 4; ++k) {
            const int u = tid + 256 * k;        // (c16, tx, j)
            const int j = u & 1;
            const int txx = (u >> 1) & 31;
            const int c16 = u >> 6;
            const uint4* src = (const uint4*)&stage[((size_t)c16 * 32 + txx) * STG_PAD + j * 8];
            uint4* dst = (uint4*)(g_V + ((size_t)(c16 * 32 + icb) * NT + nbase + txx) * 16 + j * 8);
            dst[0] = src[0];
        }
        __syncthreads();
    }
}

// ---------------------------------------------------------------------------
// Winograd GEMM: per coord z, M[o, tile] = sum_i U[z][o][i] V[z][tile][i].
// CTA 128x128, 8 warps (4x2), warp 32x64, fp16 HMMA, 3-stage cp.async.
// grid (n-tiles, o-tiles, z): 128-CTA window shares the same A (U) slab.
__global__ __launch_bounds__(256, 2)
void wino_gemm() {
    extern __shared__ __align__(128) char sm[];

    const int z  = blockIdx.z;
    const int o0 = blockIdx.y * 128;
    const int n0 = blockIdx.x * 128;
    const int tid = threadIdx.x;
    const int wid = tid >> 5;
    const int lane = tid & 31;
    const int warp_m = wid & 3;
    const int warp_n = wid >> 2;

    const uint32_t sbase = s2u(sm);

    const bool isA = (tid < 128);
    const int r = tid & 127;
    uint32_t dsw[8];
#pragma unroll
    for (int cc = 0; cc < 8; ++cc)
        dsw[cc] = (uint32_t)((isA ? 0 : TILEB) + r * 128 + ((cc ^ (r & 7)) << 4));

    const __half* aRow = g_U + (size_t)z * COUT * CIN + (size_t)(o0 + r) * CIN;
    // B base for (z, tile=n0+r): element (ic, ch) at vBase + ic*NT*16 + ch
    const __half* vBase = g_V + (size_t)z * 32 * NT * 16 + (size_t)(n0 + r) * 16;

    uint32_t offA0[2], offB0[4];
#pragma unroll
    for (int mt = 0; mt < 2; ++mt) {
        const int row = warp_m * 32 + mt * 16 + (lane & 15);
        offA0[mt] = (uint32_t)(row * 128 + (((lane >> 4) ^ (row & 7)) << 4));
    }
#pragma unroll
    for (int q = 0; q < 4; ++q) {
        const int n = warp_n * 64 + q * 16 + (lane & 7) + ((lane >> 4) << 3);
        offB0[q] = (uint32_t)(n * 128 + ((((lane >> 3) & 1) ^ (n & 7)) << 4));
    }

    float acc[2][8][4];
#pragma unroll
    for (int mt = 0; mt < 2; ++mt)
#pragma unroll
        for (int nt = 0; nt < 8; ++nt)
#pragma unroll
            for (int e = 0; e < 4; ++e) acc[mt][nt][e] = 0.f;

    auto issue = [&](int c) {
        const int s = c % NSTAGE;
        const uint32_t base = sbase + (uint32_t)(s * STAGEB);
        if (isA) {
            const __half* src = aRow + c * KC;
#pragma unroll
            for (int cc = 0; cc < 8; ++cc) cp_ca16(base + dsw[cc], src + cc * 8);
        } else {
#pragma unroll
            for (int cc = 0; cc < 8; ++cc) {
                const __half* src = vBase + (size_t)(c * 4 + (cc >> 1)) * (NT * 16)
                                          + (cc & 1) * 8;
                cp_cg16(base + dsw[cc], src);
            }
        }
        cp_commit();
    };

    issue(0);
    issue(1);

    for (int c = 0; c < NCH; ++c) {
        cp_wait1();
        __syncthreads();
        if (c + 2 < NCH) issue(c + 2);
        else cp_commit();

        const uint32_t base = sbase + (uint32_t)((c % NSTAGE) * STAGEB);
        const uint32_t bA = base;
        const uint32_t bB = base + TILEB;

#pragma unroll
        for (int j = 0; j < 4; ++j) {
            const uint32_t jx = (uint32_t)(j << 5);
            uint32_t ah[2][4], bh[4][4];
#pragma unroll
            for (int mt = 0; mt < 2; ++mt) ldsm4(ah[mt], bA + (offA0[mt] ^ jx));
#pragma unroll
            for (int q = 0; q < 4; ++q)   ldsm4(bh[q], bB + (offB0[q] ^ jx));
#pragma unroll
            for (int mt = 0; mt < 2; ++mt)
#pragma unroll
                for (int nt = 0; nt < 8; ++nt) {
                    const int q = nt >> 1;
                    const int e = (nt & 1) * 2;
                    MMA(acc[mt][nt], ah[mt], bh[q][e], bh[q][e + 1]);
                }
        }
    }

    // epilogue: fp16 store to g_M[z][o][n]
    __half* Mb = g_M + (size_t)z * COUT * NT;
#pragma unroll
    for (int mt = 0; mt < 2; ++mt) {
        const int ob = o0 + warp_m * 32 + mt * 16 + (lane >> 2);
        __half* row0 = Mb + (size_t)ob * NT + n0 + warp_n * 64;
        __half* row1 = row0 + (size_t)8 * NT;
#pragma unroll
        for (int nt = 0; nt < 8; ++nt) {
            const int w = nt * 8 + (lane & 3) * 2;
            *(__half2*)(row0 + w) = __floats2half2_rn(acc[mt][nt][0], acc[mt][nt][1]);
            *(__half2*)(row1 + w) = __floats2half2_rn(acc[mt][nt][2], acc[mt][nt][3]);
        }
    }
}

// ---------------------------------------------------------------------------
// Output transform: Y = A^T M A, then demod/bias/noise, write NCHW.
// Tile pairs per thread -> half2 loads (full 128B lines per coord stream).
__global__ __launch_bounds__(256) void out_tf(const float* __restrict__ noise,
                                              const float* __restrict__ bias,
                                              const float* __restrict__ noise_scale,
                                              float* __restrict__ out) {
    __shared__ float plane[4096];
    const int o = blockIdx.x;
    const int b = blockIdx.y;
    const int tid = threadIdx.x;

    const size_t mi0 = (size_t)o * NT + (size_t)b * 1024;
#pragma unroll
    for (int q = 0; q < 2; ++q) {
        const int pr = q * 256 + tid;       // pair index 0..511
        const int t0 = pr * 2;              // even tile
        float2 m[16];
#pragma unroll
        for (int c = 0; c < 16; ++c)
            m[c] = __half22float2(*(const __half2*)(g_M + (size_t)c * COUT * NT + mi0 + t0));
        float2 t0r[4], t1r[4];
#pragma unroll
        for (int c = 0; c < 4; ++c) {
            t0r[c].x = m[0 + c].x + m[4 + c].x + m[8 + c].x;
            t0r[c].y = m[0 + c].y + m[4 + c].y + m[8 + c].y;
            t1r[c].x = m[4 + c].x - m[8 + c].x - m[12 + c].x;
            t1r[c].y = m[4 + c].y - m[8 + c].y - m[12 + c].y;
        }
        const int tyy = t0 >> 5;
        const int col = 2 * (t0 & 31);      // multiple of 4
        float4 rowa, rowb;
        rowa.x = t0r[0].x + t0r[1].x + t0r[2].x;
        rowa.y = t0r[1].x - t0r[2].x - t0r[3].x;
        rowa.z = t0r[0].y + t0r[1].y + t0r[2].y;
        rowa.w = t0r[1].y - t0r[2].y - t0r[3].y;
        rowb.x = t1r[0].x + t1r[1].x + t1r[2].x;
        rowb.y = t1r[1].x - t1r[2].x - t1r[3].x;
        rowb.z = t1r[0].y + t1r[1].y + t1r[2].y;
        rowb.w = t1r[1].y - t1r[2].y - t1r[3].y;
        *(float4*)&plane[(2 * tyy) * 64 + col]     = rowa;
        *(float4*)&plane[(2 * tyy + 1) * 64 + col] = rowb;
    }
    __syncthreads();

    const float dd = g_d[b * COUT + o];
    const float bb = bias[o];
    const float ns = noise_scale[0];
    const float4* nz4 = (const float4*)(noise + (size_t)b * 4096);
    float4* out4 = (float4*)(out + ((size_t)(b * COUT + o)) * 4096);
#pragma unroll
    for (int k = 0; k < 4; ++k) {
        const int f4 = k * 256 + tid;
        const float4 v = ((const float4*)plane)[f4];
        const float4 nz = nz4[f4];
        float4 res;
        res.x = v.x * dd + nz.x * ns + bb;
        res.y = v.y * dd + nz.y * ns + bb;
        res.z = v.z * dd + nz.z * ns + bb;
        res.w = v.w * dd + nz.w * ns + bb;
        out4[f4] = res;
    }
}

// ---------------------------------------------------------------------------
extern "C" void kernel_launch(void* const* d_in, const int* in_sizes, int n_in,
                              void* d_out, int out_size) {
    const float* x           = (const float*)d_in[0];
    const float* y           = (const float*)d_in[1];
    const float* noise       = (const float*)d_in[2];
    const float* weight      = (const float*)d_in[3];
    const float* bias        = (const float*)d_in[4];
    const float* mod_w       = (const float*)d_in[5];
    const float* mod_b       = (const float*)d_in[6];
    const float* noise_scale = (const float*)d_in[7];
    float* out = (float*)d_out;

    cudaFuncSetAttribute(wino_gemm, cudaFuncAttributeMaxDynamicSharedMemorySize, DYN_GEMM);
    cudaFuncSetAttribute(in_tf, cudaFuncAttributeMaxDynamicSharedMemorySize, DYN_INTF);

    prep_su<<<NB + COUT, CIN>>>(y, mod_w, mod_b, weight);
    prep_d<<<NB, COUT>>>();
    in_tf<<<dim3(16, 32, NB), 256, DYN_INTF>>>(x);
    wino_gemm<<<dim3(NT / 128, COUT / 128, 16), 256, DYN_GEMM>>>();
    out_tf<<<dim3(COUT, NB), 256>>>(noise, bias, noise_scale, out);
}

// round 17
// speedup vs baseline: 1.0598x; 1.0307x over previous
#include <cuda_runtime.h>
#include <cuda_fp16.h>
#include <cstdint>

#define NB   16
#define CIN  512
#define COUT 512
#define HID  512
#define HH   64
#define WW   64
#define NT   16384                 // 16 batches x 32x32 output tiles

// GEMM tiling: CTA 128(M) x 256(N), K=512 in 8 chunks of 64
#define KC     64
#define NCH    (CIN / KC)          // 8
#define TILEBA (128 * KC * 2)      // 16384 B (A stage tile)
#define TILEBB (256 * KC * 2)      // 32768 B (B stage tile)
#define STAGEB (TILEBA + TILEBB)   // 49152 B
#define NSTAGE 4
#define DYN_GEMM (NSTAGE * STAGEB) // 196608 B

// in_tf: 16 channels x 2 tile-rows per CTA (6 input rows, 25% fewer reads)
#define XS_STRIDE 72               // floats per row: [3 pad][w=-1..64][3 pad]
#define XS_BYTES  (16 * 6 * XS_STRIDE * 4)        // 27648
#define STG_PAD   24               // halfs per stage row (16 + 8 pad, 48B)
#define STG_BYTES (16 * 32 * STG_PAD * 2)         // 24576
#define DYN_INTF  (XS_BYTES + STG_BYTES)          // 52224

// ---------------- static device scratch -------------------------------------
__device__ float g_s[NB * CIN];
__device__ float g_d[NB * COUT];
__device__ float g_w2[CIN * COUT];
__device__ __half g_U[(size_t)16 * COUT * CIN];   // [coord][o][i]
__device__ __half g_V[(size_t)16 * 32 * NT * 16]; // [coord][ic16][tile][16ch]
__device__ __half g_M[(size_t)16 * COUT * NT];    // [coord][o][tile], fp16

// ---------------- helpers ----------------------------------------------------
__device__ __forceinline__ uint32_t s2u(const void* p) {
    uint32_t a;
    asm("{ .reg .u64 t; cvta.to.shared.u64 t, %1; cvt.u32.u64 %0, t; }" : "=r"(a) : "l"(p));
    return a;
}
__device__ __forceinline__ void cp_ca16(uint32_t dst, const void* src) {
    asm volatile("cp.async.ca.shared.global [%0], [%1], 16;"
                 :: "r"(dst), "l"(src) : "memory");
}
__device__ __forceinline__ void cp_cg16(uint32_t dst, const void* src) {
    asm volatile("cp.async.cg.shared.global [%0], [%1], 16;"
                 :: "r"(dst), "l"(src) : "memory");
}
__device__ __forceinline__ void cp_commit() {
    asm volatile("cp.async.commit_group;" ::: "memory");
}
__device__ __forceinline__ void cp_wait2() {
    asm volatile("cp.async.wait_group 2;" ::: "memory");
}
__device__ __forceinline__ void cp_wait0() {
    asm volatile("cp.async.wait_group 0;" ::: "memory");
}
__device__ __forceinline__ void ldsm4(uint32_t* r, uint32_t addr) {
    asm volatile("ldmatrix.sync.aligned.m8n8.x4.shared.b16 {%0,%1,%2,%3}, [%4];"
                 : "=r"(r[0]), "=r"(r[1]), "=r"(r[2]), "=r"(r[3]) : "r"(addr));
}
#define MMA(c, a, B0, B1) \
    asm volatile("mma.sync.aligned.m16n8k16.row.col.f32.f16.f16.f32 " \
                 "{%0,%1,%2,%3},{%4,%5,%6,%7},{%8,%9},{%0,%1,%2,%3};" \
                 : "+f"((c)[0]), "+f"((c)[1]), "+f"((c)[2]), "+f"((c)[3]) \
                 : "r"((a)[0]), "r"((a)[1]), "r"((a)[2]), "r"((a)[3]), \
                   "r"(B0), "r"(B1))

// ---------------------------------------------------------------------------
// Prep 1+2 merged: blocks 0..NB-1 do style s[b,i]; blocks NB.. do U transform.
__global__ void prep_su(const float* __restrict__ y,
                        const float* __restrict__ mod_w,
                        const float* __restrict__ mod_b,
                        const float* __restrict__ weight) {
    if (blockIdx.x < NB) {
        const int b = blockIdx.x;
        const int i = threadIdx.x;
        const float ms = rsqrtf((float)HID);
        const float4* yr = (const float4*)(y + (size_t)b * HID);
        const float4* wr = (const float4*)(mod_w + (size_t)i * HID);
        float acc = 0.f;
#pragma unroll 8
        for (int h = 0; h < HID / 4; ++h) {
            float4 a = yr[h];
            float4 w = wr[h];
            acc += a.x * w.x + a.y * w.y + a.z * w.z + a.w * w.w;
        }
        g_s[b * CIN + i] = acc * ms + mod_b[i] + 1.0f;
    } else {
        const int o = blockIdx.x - NB;
        const int i = threadIdx.x;
        const float coef = rsqrtf((float)(CIN * 9));
        const float* wp = weight + ((size_t)o * CIN + i) * 9;
        float g[3][3];
        float ss = 0.f;
#pragma unroll
        for (int r = 0; r < 3; ++r)
#pragma unroll
            for (int c = 0; c < 3; ++c) {
                const float v = wp[r * 3 + c] * coef;
                g[r][c] = v;
                ss += v * v;
            }
        g_w2[i * COUT + o] = ss;

        float T[4][3];
#pragma unroll
        for (int c = 0; c < 3; ++c) {
            T[0][c] = g[0][c];
            T[1][c] = 0.5f * (g[0][c] + g[1][c] + g[2][c]);
            T[2][c] = 0.5f * (g[0][c] - g[1][c] + g[2][c]);
            T[3][c] = g[2][c];
        }
        const size_t base = (size_t)o * CIN + i;
#pragma unroll
        for (int r = 0; r < 4; ++r) {
            float u0 = T[r][0];
            float u1 = 0.5f * (T[r][0] + T[r][1] + T[r][2]);
            float u2 = 0.5f * (T[r][0] - T[r][1] + T[r][2]);
            float u3 = T[r][2];
            g_U[(size_t)(r * 4 + 0) * COUT * CIN + base] = __float2half(u0);
            g_U[(size_t)(r * 4 + 1) * COUT * CIN + base] = __float2half(u1);
            g_U[(size_t)(r * 4 + 2) * COUT * CIN + base] = __float2half(u2);
            g_U[(size_t)(r * 4 + 3) * COUT * CIN + base] = __float2half(u3);
        }
    }
}

// ---------------------------------------------------------------------------
// Prep 3: demod d[b,o]
__global__ void prep_d() {
    const int b = blockIdx.x;
    const int o = threadIdx.x;
    __shared__ float s2[CIN];
    for (int i = threadIdx.x; i < CIN; i += blockDim.x) {
        const float s = g_s[b * CIN + i];
        s2[i] = s * s;
    }
    __syncthreads();
    float acc = 0.f;
#pragma unroll 8
    for (int i = 0; i < CIN; ++i)
        acc += g_w2[i * COUT + o] * s2[i];
    g_d[b * COUT + o] = rsqrtf(acc + 1e-8f);
}

// ---------------------------------------------------------------------------
// Input transform: V[coord][ic][b*1024 + ty*32 + tx][ch] = B^T (x) B * s, fp16.
// 16 channels x 2 tile-rows per CTA (6 input rows; stage reused twice).
// grid (16 typ, 32 ic, 16 b), 256 threads.
__global__ __launch_bounds__(256) void in_tf(const float* __restrict__ x) {
    extern __shared__ __align__(16) char smraw[];
    float* xs = (float*)smraw;                       // [16 i][6 r][72]
    __half* stage = (__half*)(smraw + XS_BYTES);     // [16 c][32 tx][24]

    const int typ = blockIdx.x;                      // pair of tile-rows
    const int icb = blockIdx.y;
    const int b  = blockIdx.z;
    const int i0 = icb * 16;
    const int tid = threadIdx.x;
    const int lane = tid & 31;
    const int wid = tid >> 5;

    // zero ONLY the halo blocks (slots 0-3 and 68-71; transform reads 3..68)
    if (tid < 192) {
        const int i_l = tid / 12;
        const int rem = tid - i_l * 12;
        const int r = rem >> 1;
        const int side = rem & 1;          // 0 -> slots 0-3, 1 -> slots 68-71
        *(uint4*)&xs[(i_l * 6 + r) * XS_STRIDE + side * 68] = make_uint4(0, 0, 0, 0);
    }

    // fill interior: 6 rows per channel (rows 4*typ-1 .. 4*typ+4)
    const int r0 = 4 * typ - 1;
    const uint32_t xs_u = s2u(xs);
#pragma unroll
    for (int k = 0; k < 6; ++k) {
        const int idx = tid + 256 * k;      // (i_l, r, seg), 16*6*16 = 1536
        const int i_l = idx / 96;
        const int rem = idx - i_l * 96;
        const int r = rem >> 4;
        const int seg = rem & 15;
        const int row = r0 + r;
        const int off = (i_l * 6 + r) * XS_STRIDE + 4 + seg * 4;
        if ((unsigned)row < HH) {
            const float* src = x + (((size_t)(b * CIN + i0 + i_l)) * HH + row) * WW + seg * 4;
            cp_cg16(xs_u + (uint32_t)(off * 4), src);
        } else {
            *(uint4*)&xs[off] = make_uint4(0, 0, 0, 0);
        }
    }
    cp_commit();
    cp_wait0();
    __syncthreads();

    // two sub-tiles (ty = 2*typ + sub); stage buffer reused
#pragma unroll 1
    for (int sub = 0; sub < 2; ++sub) {
        const int tx = lane;
        float tm[2][4][4];
#pragma unroll
        for (int q = 0; q < 2; ++q) {
            const int i_l = 2 * wid + q;
            const float sc = g_s[b * CIN + i0 + i_l];
            const float* base = &xs[(i_l * 6 + sub * 2) * XS_STRIDE + 3 + 2 * tx];
            float d[4][4];
#pragma unroll
            for (int r = 0; r < 4; ++r)
#pragma unroll
                for (int c = 0; c < 4; ++c)
                    d[r][c] = base[r * XS_STRIDE + c] * sc;
#pragma unroll
            for (int c = 0; c < 4; ++c) {
                tm[q][0][c] = d[0][c] - d[2][c];
                tm[q][1][c] = d[1][c] + d[2][c];
                tm[q][2][c] = d[2][c] - d[1][c];
                tm[q][3][c] = d[1][c] - d[3][c];
            }
        }
#pragma unroll
        for (int r = 0; r < 4; ++r) {
            float v[2][4];
#pragma unroll
            for (int q = 0; q < 2; ++q) {
                v[q][0] = tm[q][r][0] - tm[q][r][2];
                v[q][1] = tm[q][r][1] + tm[q][r][2];
                v[q][2] = tm[q][r][2] - tm[q][r][1];
                v[q][3] = tm[q][r][1] - tm[q][r][3];
            }
#pragma unroll
            for (int c = 0; c < 4; ++c) {
                *(__half2*)&stage[((r * 4 + c) * 32 + tx) * STG_PAD + 2 * wid] =
                    __floats2half2_rn(v[0][c], v[1][c]);
            }
        }
        __syncthreads();

        // contiguous copy stage -> g_V[coord][icb][tile][16ch]
        const size_t nbase = (size_t)b * 1024 + (2 * typ + sub) * 32;
#pragma unroll
        for (int k = 0; k < 4; ++k) {
            const int u = tid + 256 * k;        // (c16, tx, j)
            const int j = u & 1;
            const int txx = (u >> 1) & 31;
            const int c16 = u >> 6;
            const uint4* src = (const uint4*)&stage[((size_t)c16 * 32 + txx) * STG_PAD + j * 8];
            uint4* dst = (uint4*)(g_V + ((size_t)(c16 * 32 + icb) * NT + nbase + txx) * 16 + j * 8);
            dst[0] = src[0];
        }
        __syncthreads();
    }
}

// ---------------------------------------------------------------------------
// Winograd GEMM: per coord z, M[o, tile] = sum_i U[z][o][i] V[z][tile][i].
// CTA 128(M) x 256(N), 8 warps (2x4), warp tile 64x64, 4-stage cp.async.
// 1 CTA/SM (regs+smem); frag traffic 128 B/HMMA (vs 192 at 32x64 tiles).
__global__ __launch_bounds__(256)
void wino_gemm() {
    extern __shared__ __align__(128) char sm[];

    const int z  = blockIdx.z;
    const int o0 = blockIdx.y * 128;
    const int n0 = blockIdx.x * 256;
    const int tid = threadIdx.x;
    const int wid = tid >> 5;
    const int lane = tid & 31;
    const int warp_m = wid & 1;    // 0..1 -> 64-row m block
    const int warp_n = wid >> 1;   // 0..3 -> 64-col n block

    const uint32_t sbase = s2u(sm);

    // ---- cp.async geometry ----
    // B: every thread owns B row rB = tid (8 x 16B, swizzled)
    // A: thread owns half of A row rA = tid>>1, chunks ccA = (tid&1)*4 + m
    const int rB = tid;
    const int rA = tid >> 1;
    uint32_t dswB[8], dswA[4];
#pragma unroll
    for (int cc = 0; cc < 8; ++cc)
        dswB[cc] = (uint32_t)(TILEBA + rB * 128 + ((cc ^ (rB & 7)) << 4));
#pragma unroll
    for (int m = 0; m < 4; ++m) {
        const int ccA = (tid & 1) * 4 + m;
        dswA[m] = (uint32_t)(rA * 128 + ((ccA ^ (rA & 7)) << 4));
    }
    const int ccA0 = (tid & 1) * 4;

    const __half* aRow = g_U + (size_t)z * COUT * CIN + (size_t)(o0 + rA) * CIN;
    const __half* vBase = g_V + (size_t)z * 32 * NT * 16 + (size_t)(n0 + rB) * 16;

    // ---- ldmatrix base offsets (j=0); addr(j) = addr(0) ^ (j<<5) ----
    uint32_t offA0[4], offB0[4];
#pragma unroll
    for (int mt = 0; mt < 4; ++mt) {
        const int row = warp_m * 64 + mt * 16 + (lane & 15);
        offA0[mt] = (uint32_t)(row * 128 + (((lane >> 4) ^ (row & 7)) << 4));
    }
#pragma unroll
    for (int q = 0; q < 4; ++q) {
        const int n = warp_n * 64 + q * 16 + (lane & 7) + ((lane >> 4) << 3);
        offB0[q] = (uint32_t)(TILEBA + n * 128 + ((((lane >> 3) & 1) ^ (n & 7)) << 4));
    }

    float acc[4][8][4];
#pragma unroll
    for (int mt = 0; mt < 4; ++mt)
#pragma unroll
        for (int nt = 0; nt < 8; ++nt)
#pragma unroll
            for (int e = 0; e < 4; ++e) acc[mt][nt][e] = 0.f;

    auto issue = [&](int c) {
        const int s = c & (NSTAGE - 1);
        const uint32_t base = sbase + (uint32_t)(s * STAGEB);
        // A: 4 x 16B
        const __half* srcA = aRow + c * KC + ccA0 * 8;
#pragma unroll
        for (int m = 0; m < 4; ++m)
            cp_ca16(base + dswA[m], srcA + m * 8);
        // B: 8 x 16B
#pragma unroll
        for (int cc = 0; cc < 8; ++cc) {
            const __half* src = vBase + (size_t)(c * 4 + (cc >> 1)) * (NT * 16)
                                      + (cc & 1) * 8;
            cp_cg16(base + dswB[cc], src);
        }
        cp_commit();
    };

    issue(0);
    issue(1);
    issue(2);

#pragma unroll 1
    for (int c = 0; c < NCH; ++c) {
        cp_wait2();
        __syncthreads();
        if (c + 3 < NCH) issue(c + 3);
        else cp_commit();

        const uint32_t base = sbase + (uint32_t)((c & (NSTAGE - 1)) * STAGEB);

#pragma unroll
        for (int j = 0; j < 4; ++j) {
            const uint32_t jx = (uint32_t)(j << 5);
            uint32_t ah[4][4], bh[4][4];
#pragma unroll
            for (int mt = 0; mt < 4; ++mt) ldsm4(ah[mt], base + (offA0[mt] ^ jx));
#pragma unroll
            for (int q = 0; q < 4; ++q)   ldsm4(bh[q], base + (offB0[q] ^ jx));
#pragma unroll
            for (int mt = 0; mt < 4; ++mt)
#pragma unroll
                for (int nt = 0; nt < 8; ++nt) {
                    const int q = nt >> 1;
                    const int e = (nt & 1) * 2;
                    MMA(acc[mt][nt], ah[mt], bh[q][e], bh[q][e + 1]);
                }
        }
        __syncthreads();
    }

    // epilogue: fp16 store to g_M[z][o][n]
    __half* Mb = g_M + (size_t)z * COUT * NT;
#pragma unroll
    for (int mt = 0; mt < 4; ++mt) {
        const int ob = o0 + warp_m * 64 + mt * 16 + (lane >> 2);
        __half* row0 = Mb + (size_t)ob * NT + n0 + warp_n * 64;
        __half* row1 = row0 + (size_t)8 * NT;
#pragma unroll
        for (int nt = 0; nt < 8; ++nt) {
            const int w = nt * 8 + (lane & 3) * 2;
            *(__half2*)(row0 + w) = __floats2half2_rn(acc[mt][nt][0], acc[mt][nt][1]);
            *(__half2*)(row1 + w) = __floats2half2_rn(acc[mt][nt][2], acc[mt][nt][3]);
        }
    }
}

// ---------------------------------------------------------------------------
// Output transform: Y = A^T M A, then demod/bias/noise, write NCHW.
__global__ __launch_bounds__(256) void out_tf(const float* __restrict__ noise,
                                              const float* __restrict__ bias,
                                              const float* __restrict__ noise_scale,
                                              float* __restrict__ out) {
    __shared__ float plane[4096];
    const int o = blockIdx.x;
    const int b = blockIdx.y;
    const int tid = threadIdx.x;

    const size_t mi0 = (size_t)o * NT + (size_t)b * 1024;
#pragma unroll
    for (int q = 0; q < 2; ++q) {
        const int pr = q * 256 + tid;       // pair index 0..511
        const int t0 = pr * 2;              // even tile
        float2 m[16];
#pragma unroll
        for (int c = 0; c < 16; ++c)
            m[c] = __half22float2(*(const __half2*)(g_M + (size_t)c * COUT * NT + mi0 + t0));
        float2 t0r[4], t1r[4];
#pragma unroll
        for (int c = 0; c < 4; ++c) {
            t0r[c].x = m[0 + c].x + m[4 + c].x + m[8 + c].x;
            t0r[c].y = m[0 + c].y + m[4 + c].y + m[8 + c].y;
            t1r[c].x = m[4 + c].x - m[8 + c].x - m[12 + c].x;
            t1r[c].y = m[4 + c].y - m[8 + c].y - m[12 + c].y;
        }
        const int tyy = t0 >> 5;
        const int col = 2 * (t0 & 31);      // multiple of 4
        float4 rowa, rowb;
        rowa.x = t0r[0].x + t0r[1].x + t0r[2].x;
        rowa.y = t0r[1].x - t0r[2].x - t0r[3].x;
        rowa.z = t0r[0].y + t0r[1].y + t0r[2].y;
        rowa.w = t0r[1].y - t0r[2].y - t0r[3].y;
        rowb.x = t1r[0].x + t1r[1].x + t1r[2].x;
        rowb.y = t1r[1].x - t1r[2].x - t1r[3].x;
        rowb.z = t1r[0].y + t1r[1].y + t1r[2].y;
        rowb.w = t1r[1].y - t1r[2].y - t1r[3].y;
        *(float4*)&plane[(2 * tyy) * 64 + col]     = rowa;
        *(float4*)&plane[(2 * tyy + 1) * 64 + col] = rowb;
    }
    __syncthreads();

    const float dd = g_d[b * COUT + o];
    const float bb = bias[o];
    const float ns = noise_scale[0];
    const float4* nz4 = (const float4*)(noise + (size_t)b * 4096);
    float4* out4 = (float4*)(out + ((size_t)(b * COUT + o)) * 4096);
#pragma unroll
    for (int k = 0; k < 4; ++k) {
        const int f4 = k * 256 + tid;
        const float4 v = ((const float4*)plane)[f4];
        const float4 nz = nz4[f4];
        float4 res;
        res.x = v.x * dd + nz.x * ns + bb;
        res.y = v.y * dd + nz.y * ns + bb;
        res.z = v.z * dd + nz.z * ns + bb;
        res.w = v.w * dd + nz.w * ns + bb;
        out4[f4] = res;
    }
}

// ---------------------------------------------------------------------------
extern "C" void kernel_launch(void* const* d_in, const int* in_sizes, int n_in,
                              void* d_out, int out_size) {
    const float* x           = (const float*)d_in[0];
    const float* y           = (const float*)d_in[1];
    const float* noise       = (const float*)d_in[2];
    const float* weight      = (const float*)d_in[3];
    const float* bias        = (const float*)d_in[4];
    const float* mod_w       = (const float*)d_in[5];
    const float* mod_b       = (const float*)d_in[6];
    const float* noise_scale = (const float*)d_in[7];
    float* out = (float*)d_out;

    cudaFuncSetAttribute(wino_gemm, cudaFuncAttributeMaxDynamicSharedMemorySize, DYN_GEMM);
    cudaFuncSetAttribute(in_tf, cudaFuncAttributeMaxDynamicSharedMemorySize, DYN_INTF);

    prep_su<<<NB + COUT, CIN>>>(y, mod_w, mod_b, weight);
    prep_d<<<NB, COUT>>>();
    in_tf<<<dim3(16, 32, NB), 256, DYN_INTF>>>(x);
    wino_gemm<<<dim3(NT / 256, COUT / 128, 16), 256, DYN_GEMM>>>();
    out_tf<<<dim3(COUT, NB), 256>>>(noise, bias, noise_scale, out);
}